// round 1
// baseline (speedup 1.0000x reference)
#include <cuda_runtime.h>

// Recurrent channel attention, sequential scan over T.
// One persistent CTA, 512 threads (16 warps), thread c owns channel c.
//   C=512, T=8192, M=5, H=16, momentum=0.05
//
// Per step t:
//   z[c]   = y_prev[c] + y[c,t]                      (smem exchange)
//   h[j]   = relu( sum_c z[c]*W1[c,j] + b1[j] )      (warp j reduces)
//   q[c]   = sum_j h[j]*W2[j,c] + b2[c]
//   ema[c,m] = 0.95*ema[c,m] + 0.05*q[c]*K[t,c,m]
//   s      = sum_{c,m} ema^2                          (block reduce)
//   out[c,t] = (sum_m ema[c,m]*V[t,c,m]) / (sqrt(s) + bias_t*1e-12)
// where bias_t = 1 - 0.95^t  (exactly matches reference normalization).

#define CCH 512
#define TT  8192
#define MM  5
#define HID 16
#define NWARP 16

__global__ __launch_bounds__(512, 1)
void rca_kernel(const float* __restrict__ y,
                const float* __restrict__ Kp,
                const float* __restrict__ Vp,
                const float* __restrict__ W1,
                const float* __restrict__ b1,
                const float* __restrict__ W2,
                const float* __restrict__ b2,
                float* __restrict__ out)
{
    __shared__ float sz[CCH];   // z vector (y_prev + y_t)
    __shared__ float sh[HID];   // relu'd hidden layer
    __shared__ float ss[NWARP]; // per-warp norm partials

    const int tid  = threadIdx.x;
    const int wid  = tid >> 5;
    const int lane = tid & 31;

    // --- preload weights into registers ---
    // MLP1: warp j computes h[j]; lane l accumulates channels l+32*i.
    float w1r[16];
#pragma unroll
    for (int i = 0; i < 16; i++)
        w1r[i] = W1[(lane + 32 * i) * HID + wid];
    // MLP2: thread c holds column c of W2.
    float w2r[16];
#pragma unroll
    for (int j = 0; j < 16; j++)
        w2r[j] = W2[j * CCH + tid];
    const float b1w = b1[wid];
    const float b2c = b2[tid];

    // --- recurrent state ---
    float ema[MM];
#pragma unroll
    for (int m = 0; m < MM; m++) ema[m] = 0.f;
    float y_prev = 0.f;
    float pw = 1.f;   // 0.95^t

    // --- prefetch t = 0 ---
    float ycur = y[tid * TT + 0];
    float kc[MM], vc[MM];
    {
        const float* kb = Kp + tid * MM;
        const float* vb = Vp + tid * MM;
#pragma unroll
        for (int m = 0; m < MM; m++) { kc[m] = kb[m]; vc[m] = vb[m]; }
    }

    float* outp = out + tid * TT;

    for (int t = 0; t < TT; t++) {
        // publish z[c]
        sz[tid] = y_prev + ycur;

        // prefetch t+1 (independent of state; overlaps the whole step)
        const int tn = (t + 1 < TT) ? (t + 1) : t;
        float ynx = y[tid * TT + tn];
        float kn[MM], vn[MM];
        {
            const float* kb = Kp + (size_t)tn * (CCH * MM) + tid * MM;
            const float* vb = Vp + (size_t)tn * (CCH * MM) + tid * MM;
#pragma unroll
            for (int m = 0; m < MM; m++) { kn[m] = kb[m]; vn[m] = vb[m]; }
        }

        __syncthreads();   // bar1: z visible

        // ---- MLP1: warp wid computes h[wid] ----
        float a0 = 0.f, a1 = 0.f, a2 = 0.f, a3 = 0.f;
#pragma unroll
        for (int i = 0; i < 16; i += 4) {
            a0 = fmaf(sz[lane + 32 * (i + 0)], w1r[i + 0], a0);
            a1 = fmaf(sz[lane + 32 * (i + 1)], w1r[i + 1], a1);
            a2 = fmaf(sz[lane + 32 * (i + 2)], w1r[i + 2], a2);
            a3 = fmaf(sz[lane + 32 * (i + 3)], w1r[i + 3], a3);
        }
        float acc = (a0 + a1) + (a2 + a3);
        acc += __shfl_down_sync(0xffffffffu, acc, 16);
        acc += __shfl_down_sync(0xffffffffu, acc, 8);
        acc += __shfl_down_sync(0xffffffffu, acc, 4);
        acc += __shfl_down_sync(0xffffffffu, acc, 2);
        acc += __shfl_down_sync(0xffffffffu, acc, 1);
        if (lane == 0) sh[wid] = fmaxf(acc + b1w, 0.f);

        __syncthreads();   // bar2: h visible

        // ---- MLP2: q[c] ----
        float q0 = b2c, q1 = 0.f, q2 = 0.f, q3 = 0.f;
#pragma unroll
        for (int j = 0; j < 16; j += 4) {
            q0 = fmaf(sh[j + 0], w2r[j + 0], q0);
            q1 = fmaf(sh[j + 1], w2r[j + 1], q1);
            q2 = fmaf(sh[j + 2], w2r[j + 2], q2);
            q3 = fmaf(sh[j + 3], w2r[j + 3], q3);
        }
        const float q = (q0 + q1) + (q2 + q3);

        // ---- EMA update + local partials ----
        pw *= 0.95f;
        const float bias = 1.f - pw;
        float sp = 0.f, dot = 0.f;
#pragma unroll
        for (int m = 0; m < MM; m++) {
            const float att = q * kc[m];
            ema[m] = fmaf(0.95f, ema[m], 0.05f * att);
            sp  = fmaf(ema[m], ema[m], sp);
            dot = fmaf(ema[m], vc[m], dot);
        }

        // ---- block reduce s = sum(ema^2) ----
        sp += __shfl_down_sync(0xffffffffu, sp, 16);
        sp += __shfl_down_sync(0xffffffffu, sp, 8);
        sp += __shfl_down_sync(0xffffffffu, sp, 4);
        sp += __shfl_down_sync(0xffffffffu, sp, 2);
        sp += __shfl_down_sync(0xffffffffu, sp, 1);
        if (lane == 0) ss[wid] = sp;

        __syncthreads();   // bar3: partials visible

        float s0 = 0.f, s1 = 0.f, s2 = 0.f, s3 = 0.f;
#pragma unroll
        for (int w = 0; w < NWARP; w += 4) {
            s0 += ss[w + 0]; s1 += ss[w + 1];
            s2 += ss[w + 2]; s3 += ss[w + 3];
        }
        const float s = (s0 + s1) + (s2 + s3);

        const float denom = sqrtf(s) + bias * 1e-12f;
        const float ynew = dot / denom;

        outp[t] = ynew;
        y_prev = ynew;

        // rotate prefetch buffers
        ycur = ynx;
#pragma unroll
        for (int m = 0; m < MM; m++) { kc[m] = kn[m]; vc[m] = vn[m]; }
    }
}

extern "C" void kernel_launch(void* const* d_in, const int* in_sizes, int n_in,
                              void* d_out, int out_size) {
    const float* y  = (const float*)d_in[0];
    const float* Kp = (const float*)d_in[1];
    const float* Vp = (const float*)d_in[2];
    const float* W1 = (const float*)d_in[3];
    const float* b1 = (const float*)d_in[4];
    const float* W2 = (const float*)d_in[5];
    const float* b2 = (const float*)d_in[6];
    float* out = (float*)d_out;
    rca_kernel<<<1, 512>>>(y, Kp, Vp, W1, b1, W2, b2, out);
}

// round 2
// speedup vs baseline: 1.1837x; 1.1837x over previous
#include <cuda_runtime.h>

#define CCH 512
#define TT  8192
#define MM  5

// scratch (static device globals — allowed)
__device__ float g_U[TT * 16];    // U[t,j] = b1[j] + sum_c y[c,t]*W1[c,j]
__device__ float g_invd[TT];      // 1/sqrt(s_t) per step (0 if s==0)

// ---------------- kernel 1: precompute U (parallel, all SMs) ----------------
__global__ void precompute_U(const float* __restrict__ y,
                             const float* __restrict__ W1,
                             const float* __restrict__ b1)
{
    const int j = threadIdx.x & 15;
    const int t = blockIdx.x * 16 + (threadIdx.x >> 4);
    float a0 = b1[j], a1 = 0.f, a2 = 0.f, a3 = 0.f;
#pragma unroll 4
    for (int c = 0; c < CCH; c += 4) {
        a0 = fmaf(y[(c + 0) * TT + t], W1[(c + 0) * 16 + j], a0);
        a1 = fmaf(y[(c + 1) * TT + t], W1[(c + 1) * 16 + j], a1);
        a2 = fmaf(y[(c + 2) * TT + t], W1[(c + 2) * 16 + j], a2);
        a3 = fmaf(y[(c + 3) * TT + t], W1[(c + 3) * 16 + j], a3);
    }
    g_U[t * 16 + j] = (a0 + a1) + (a2 + a3);
}

// ---------------- kernel 2: sequential recurrence, 1 CTA ----------------
// Per iteration t (0..TT inclusive):
//   B: warp j reduces g[j] = sum_c dot_prev[c]*W1[c,j]  (smem dot, shuffle)
//      + s = sum ss[w]  (interleaved chain);  inv = rsqrt(s)
//      h[j] = relu(g*inv + U[t]);  invd[t-1] = inv
//   bar
//   C: q[c] = b2[c] + sum_j h[j]*W2[j,c]
//   A: ema update with K[t]; dot,sp; publish sdot, ss; STG raw dot
//   bar
__global__ __launch_bounds__(512, 1)
void rca_kernel(const float* __restrict__ Kp,
                const float* __restrict__ Vp,
                const float* __restrict__ W1,
                const float* __restrict__ W2,
                const float* __restrict__ b2,
                float* __restrict__ out)
{
    __shared__ float sdot[CCH];
    __shared__ float ss[16];
    __shared__ float sh[16];

    const int tid  = threadIdx.x;
    const int wid  = tid >> 5;
    const int lane = tid & 31;

    // weights in registers
    float w1r[16];                     // W1[lane+32i][wid]
#pragma unroll
    for (int i = 0; i < 16; i++) w1r[i] = W1[(lane + 32 * i) * 16 + wid];
    float w2r[16];                     // W2[j][tid]
#pragma unroll
    for (int j = 0; j < 16; j++) w2r[j] = W2[j * CCH + tid];
    const float b2c = b2[tid];

    float ema[MM];
#pragma unroll
    for (int m = 0; m < MM; m++) ema[m] = 0.f;

    // depth-3 prefetch buffers (iteration t uses slot t%3)
    float kb[3][MM], vb[3][MM], ub[3];
    const float* kbase = Kp + tid * MM;
    const float* vbase = Vp + tid * MM;
#pragma unroll
    for (int i = 0; i < 3; i++) {
        const int off = i * (CCH * MM);
#pragma unroll
        for (int m = 0; m < MM; m++) {
            kb[i][m] = kbase[off + m];
            vb[i][m] = vbase[off + m];
        }
        ub[i] = g_U[i * 16 + wid];
    }

    sdot[tid] = 0.f;
    if (tid < 16) ss[tid] = 0.f;
    __syncthreads();

    float* outp = out + tid * TT;

    // 8193 iterations total (last one only finishes the norm for t=TT-1)
    for (int t0 = 0; t0 < TT + 3; t0 += 3) {
#pragma unroll
        for (int i = 0; i < 3; i++) {
            const int t = t0 + i;

            // ---------- Phase B ----------
            float g0 = 0.f, g1 = 0.f, g2 = 0.f, g3 = 0.f;
#pragma unroll
            for (int ii = 0; ii < 16; ii += 4) {
                g0 = fmaf(sdot[lane + 32 * (ii + 0)], w1r[ii + 0], g0);
                g1 = fmaf(sdot[lane + 32 * (ii + 1)], w1r[ii + 1], g1);
                g2 = fmaf(sdot[lane + 32 * (ii + 2)], w1r[ii + 2], g2);
                g3 = fmaf(sdot[lane + 32 * (ii + 3)], w1r[ii + 3], g3);
            }
            float g = (g0 + g1) + (g2 + g3);
            float s = ss[lane & 15];
            // interleaved butterflies: g (5 rounds), s (4 rounds)
            g += __shfl_xor_sync(0xffffffffu, g, 16);
            s += __shfl_xor_sync(0xffffffffu, s, 8);
            g += __shfl_xor_sync(0xffffffffu, g, 8);
            s += __shfl_xor_sync(0xffffffffu, s, 4);
            g += __shfl_xor_sync(0xffffffffu, g, 4);
            s += __shfl_xor_sync(0xffffffffu, s, 2);
            g += __shfl_xor_sync(0xffffffffu, g, 2);
            s += __shfl_xor_sync(0xffffffffu, s, 1);
            g += __shfl_xor_sync(0xffffffffu, g, 1);

            const float inv = (s > 0.f) ? rsqrtf(s) : 0.f;
            if (lane == 0) {
                sh[wid] = fmaxf(fmaf(g, inv, ub[i]), 0.f);
                if (wid == 0 && t > 0) g_invd[t - 1] = inv;
            }
            if (t == TT) return;   // uniform exit after final invd store

            __syncthreads();       // bar: h visible

            // ---------- Phase C ----------
            const float4 h0 = *(const float4*)&sh[0];
            const float4 h1 = *(const float4*)&sh[4];
            const float4 h2 = *(const float4*)&sh[8];
            const float4 h3 = *(const float4*)&sh[12];
            float q0 = b2c, q1 = 0.f, q2 = 0.f, q3 = 0.f;
            q0 = fmaf(h0.x, w2r[0],  q0); q1 = fmaf(h0.y, w2r[1],  q1);
            q2 = fmaf(h0.z, w2r[2],  q2); q3 = fmaf(h0.w, w2r[3],  q3);
            q0 = fmaf(h1.x, w2r[4],  q0); q1 = fmaf(h1.y, w2r[5],  q1);
            q2 = fmaf(h1.z, w2r[6],  q2); q3 = fmaf(h1.w, w2r[7],  q3);
            q0 = fmaf(h2.x, w2r[8],  q0); q1 = fmaf(h2.y, w2r[9],  q1);
            q2 = fmaf(h2.z, w2r[10], q2); q3 = fmaf(h2.w, w2r[11], q3);
            q0 = fmaf(h3.x, w2r[12], q0); q1 = fmaf(h3.y, w2r[13], q1);
            q2 = fmaf(h3.z, w2r[14], q2); q3 = fmaf(h3.w, w2r[15], q3);
            const float q = (q0 + q1) + (q2 + q3);

            // ---------- Phase A ----------
            const float qm = 0.05f * q;
            float dot = 0.f, sp = 0.f;
#pragma unroll
            for (int m = 0; m < MM; m++) {
                ema[m] = fmaf(0.95f, ema[m], qm * kb[i][m]);
                dot = fmaf(ema[m], vb[i][m], dot);
                sp  = fmaf(ema[m], ema[m], sp);
            }
            sdot[tid] = dot;
            outp[t] = dot;          // raw; scaled by invd[t] in post-pass

            // prefetch t+3 into this slot (3-step lead hides DRAM)
            {
                const int tn  = (t + 3 < TT) ? (t + 3) : (TT - 1);
                const int off = tn * (CCH * MM);
#pragma unroll
                for (int m = 0; m < MM; m++) {
                    kb[i][m] = kbase[off + m];
                    vb[i][m] = vbase[off + m];
                }
                ub[i] = g_U[tn * 16 + wid];
            }

            // warp-reduce sp -> ss[wid]
            sp += __shfl_xor_sync(0xffffffffu, sp, 16);
            sp += __shfl_xor_sync(0xffffffffu, sp, 8);
            sp += __shfl_xor_sync(0xffffffffu, sp, 4);
            sp += __shfl_xor_sync(0xffffffffu, sp, 2);
            sp += __shfl_xor_sync(0xffffffffu, sp, 1);
            if (lane == 0) ss[wid] = sp;

            __syncthreads();       // bar: sdot/ss visible for next B
        }
    }
}

// ---------------- kernel 3: scale out by invd[t] (parallel) ----------------
__global__ void scale_out(float* __restrict__ out)
{
    const int idx = blockIdx.x * blockDim.x + threadIdx.x;  // [c][t], t fastest
    out[idx] *= g_invd[idx & (TT - 1)];
}

extern "C" void kernel_launch(void* const* d_in, const int* in_sizes, int n_in,
                              void* d_out, int out_size) {
    const float* y  = (const float*)d_in[0];
    const float* Kp = (const float*)d_in[1];
    const float* Vp = (const float*)d_in[2];
    const float* W1 = (const float*)d_in[3];
    const float* b1 = (const float*)d_in[4];
    const float* W2 = (const float*)d_in[5];
    const float* b2 = (const float*)d_in[6];
    float* out = (float*)d_out;

    precompute_U<<<TT / 16, 256>>>(y, W1, b1);
    rca_kernel<<<1, 512>>>(Kp, Vp, W1, W2, b2, out);
    scale_out<<<(CCH * TT) / 256, 256>>>(out);
}

// round 5
// speedup vs baseline: 1.1856x; 1.0016x over previous
#include <cuda_runtime.h>

#define CCH 512
#define TT  8192
#define MM  5

// ---- static device scratch (module-load allocated; allowed) ----
__device__ float  g_U[TT * 16];          // U[t,j] = b1[j] + W1^T y_t
__device__ float  g_invd[TT];            // rsqrt(s_t)
__device__ float4 g_KV4[TT * CCH * 2];   // per (t,c): {k0..3}, {v0..3}
__device__ float2 g_KV1[TT * CCH];       // per (t,c): {k4, v4}

// ---------------- repack K,V into vector-friendly layout ----------------
__global__ void repack_kv(const float* __restrict__ K, const float* __restrict__ V)
{
    const int idx = blockIdx.x * blockDim.x + threadIdx.x;   // t*512 + c
    const long b = (long)idx * 5;
    g_KV4[2 * idx + 0] = make_float4(K[b], K[b + 1], K[b + 2], K[b + 3]);
    g_KV4[2 * idx + 1] = make_float4(V[b], V[b + 1], V[b + 2], V[b + 3]);
    g_KV1[idx] = make_float2(K[b + 4], V[b + 4]);
}

// ---------------- precompute U (parallel) ----------------
__global__ void precompute_U(const float* __restrict__ y,
                             const float* __restrict__ W1,
                             const float* __restrict__ b1)
{
    const int j  = threadIdx.x & 15;
    const int t4 = blockIdx.x * 32 + (threadIdx.x >> 4);
    const int t0 = t4 * 4;
    const float bj = b1[j];
    float a0 = bj, a1 = bj, a2 = bj, a3 = bj;
#pragma unroll 8
    for (int c = 0; c < CCH; c++) {
        const float4 yv = *(const float4*)&y[c * TT + t0];
        const float w = W1[c * 16 + j];
        a0 = fmaf(yv.x, w, a0);
        a1 = fmaf(yv.y, w, a1);
        a2 = fmaf(yv.z, w, a2);
        a3 = fmaf(yv.w, w, a3);
    }
    g_U[(t0 + 0) * 16 + j] = a0;
    g_U[(t0 + 1) * 16 + j] = a1;
    g_U[(t0 + 2) * 16 + j] = a2;
    g_U[(t0 + 3) * 16 + j] = a3;
}

// ---------------- sequential recurrence, 1 CTA ----------------
__global__ __launch_bounds__(512, 1)
void rca_kernel(const float* __restrict__ W1,
                const float* __restrict__ W2,
                const float* __restrict__ b2,
                float* __restrict__ out)
{
    __shared__ float sdot[CCH];
    __shared__ float ss[16];
    __shared__ float sh[16];

    const int tid  = threadIdx.x;
    const int wid  = tid >> 5;
    const int lane = tid & 31;

    // B-phase channel mapping: lane handles c = 4*lane + 128*ii + k (conflict-free LDS.128)
    float w1r[16];
#pragma unroll
    for (int ii = 0; ii < 4; ii++)
#pragma unroll
        for (int k = 0; k < 4; k++)
            w1r[4 * ii + k] = W1[(4 * lane + 128 * ii + k) * 16 + wid];

    float w2r[16];
#pragma unroll
    for (int j = 0; j < 16; j++) w2r[j] = W2[j * CCH + tid];
    const float b2c = b2[tid];

    float e0 = 0.f, e1 = 0.f, e2 = 0.f, e3 = 0.f, e4 = 0.f;   // ema

    // depth-3 prefetch buffers
    float4 kb[3], vb[3];
    float2 kv1[3];
    float  ub[3];
#pragma unroll
    for (int i = 0; i < 3; i++) {
        const int idx = i * CCH + tid;
        kb[i]  = g_KV4[2 * idx + 0];
        vb[i]  = g_KV4[2 * idx + 1];
        kv1[i] = g_KV1[idx];
        ub[i]  = g_U[i * 16 + wid];
    }

    sdot[tid] = 0.f;
    if (tid < 16) ss[tid] = 0.f;
    __syncthreads();

    float* outp = out + tid * TT;
    const float4* sd4 = (const float4*)sdot;

    for (int t0 = 0; t0 < TT + 3; t0 += 3) {
#pragma unroll
        for (int i = 0; i < 3; i++) {
            const int t = t0 + i;

            // ---------- B: g[wid] = sum_c dot_prev[c]*W1[c,wid]; s = sum ema^2 ----------
            float g0 = 0.f, g1 = 0.f, g2 = 0.f, g3 = 0.f;
#pragma unroll
            for (int ii = 0; ii < 4; ii++) {
                const float4 d = sd4[lane + 32 * ii];
                g0 = fmaf(d.x, w1r[4 * ii + 0], g0);
                g1 = fmaf(d.y, w1r[4 * ii + 1], g1);
                g2 = fmaf(d.z, w1r[4 * ii + 2], g2);
                g3 = fmaf(d.w, w1r[4 * ii + 3], g3);
            }
            float g = (g0 + g1) + (g2 + g3);
            float s = ss[lane & 15];
            // interleaved butterflies: g (5 rounds), s (4 rounds) — chains pipeline
            g += __shfl_xor_sync(0xffffffffu, g, 16);
            s += __shfl_xor_sync(0xffffffffu, s, 8);
            g += __shfl_xor_sync(0xffffffffu, g, 8);
            s += __shfl_xor_sync(0xffffffffu, s, 4);
            g += __shfl_xor_sync(0xffffffffu, g, 4);
            s += __shfl_xor_sync(0xffffffffu, s, 2);
            g += __shfl_xor_sync(0xffffffffu, g, 2);
            s += __shfl_xor_sync(0xffffffffu, s, 1);
            g += __shfl_xor_sync(0xffffffffu, g, 1);

            const float inv = rsqrtf(fmaxf(s, 1e-37f));
            if (lane == 0) {
                sh[wid] = fmaxf(fmaf(g, inv, ub[i]), 0.f);
                if (wid == 0 && t > 0) g_invd[t - 1] = inv;
            }
            if (t == TT) return;

            __syncthreads();   // sh visible; also orders ss/sdot reads before A writes

            // ---------- C: q[c] = b2[c] + sum_j h[j]*W2[j,c] ----------
            const float4 h0 = *(const float4*)&sh[0];
            const float4 h1 = *(const float4*)&sh[4];
            const float4 h2 = *(const float4*)&sh[8];
            const float4 h3 = *(const float4*)&sh[12];
            float q0 = b2c, q1 = 0.f, q2 = 0.f, q3 = 0.f;
            q0 = fmaf(h0.x, w2r[0],  q0); q1 = fmaf(h0.y, w2r[1],  q1);
            q2 = fmaf(h0.z, w2r[2],  q2); q3 = fmaf(h0.w, w2r[3],  q3);
            q0 = fmaf(h1.x, w2r[4],  q0); q1 = fmaf(h1.y, w2r[5],  q1);
            q2 = fmaf(h1.z, w2r[6],  q2); q3 = fmaf(h1.w, w2r[7],  q3);
            q0 = fmaf(h2.x, w2r[8],  q0); q1 = fmaf(h2.y, w2r[9],  q1);
            q2 = fmaf(h2.z, w2r[10], q2); q3 = fmaf(h2.w, w2r[11], q3);
            q0 = fmaf(h3.x, w2r[12], q0); q1 = fmaf(h3.y, w2r[13], q1);
            q2 = fmaf(h3.z, w2r[14], q2); q3 = fmaf(h3.w, w2r[15], q3);
            const float qm = 0.05f * ((q0 + q1) + (q2 + q3));

            // ---------- A: ema update, dot, sp ----------
            const float4 k4 = kb[i], v4 = vb[i];
            const float2 x1 = kv1[i];
            e0 = fmaf(0.95f, e0, qm * k4.x);
            e1 = fmaf(0.95f, e1, qm * k4.y);
            e2 = fmaf(0.95f, e2, qm * k4.z);
            e3 = fmaf(0.95f, e3, qm * k4.w);
            e4 = fmaf(0.95f, e4, qm * x1.x);
            float dot = e0 * v4.x;
            dot = fmaf(e1, v4.y, dot);
            dot = fmaf(e2, v4.z, dot);
            dot = fmaf(e3, v4.w, dot);
            dot = fmaf(e4, x1.y, dot);
            float sp = e0 * e0;
            sp = fmaf(e1, e1, sp);
            sp = fmaf(e2, e2, sp);
            sp = fmaf(e3, e3, sp);
            sp = fmaf(e4, e4, sp);

            sdot[tid] = dot;
            outp[t] = dot;                       // raw; scaled in post-pass

            // prefetch t+3 into this slot (overlaps sp reduce + barrier)
            {
                const int tn = (t + 3 < TT) ? (t + 3) : (TT - 1);
                const int idx = tn * CCH + tid;
                kb[i]  = g_KV4[2 * idx + 0];
                vb[i]  = g_KV4[2 * idx + 1];
                kv1[i] = g_KV1[idx];
                ub[i]  = g_U[tn * 16 + wid];
            }

            // warp-reduce sp -> ss[wid]
            sp += __shfl_xor_sync(0xffffffffu, sp, 16);
            sp += __shfl_xor_sync(0xffffffffu, sp, 8);
            sp += __shfl_xor_sync(0xffffffffu, sp, 4);
            sp += __shfl_xor_sync(0xffffffffu, sp, 2);
            sp += __shfl_xor_sync(0xffffffffu, sp, 1);
            if (lane == 0) ss[wid] = sp;

            __syncthreads();   // sdot/ss visible for next B
        }
    }
}

// ---------------- scale out by invd[t] (parallel) ----------------
__global__ void scale_out(float* __restrict__ out)
{
    const int idx = blockIdx.x * blockDim.x + threadIdx.x;   // c*TT + t
    out[idx] *= g_invd[idx & (TT - 1)];
}

extern "C" void kernel_launch(void* const* d_in, const int* in_sizes, int n_in,
                              void* d_out, int out_size) {
    const float* y  = (const float*)d_in[0];
    const float* Kp = (const float*)d_in[1];
    const float* Vp = (const float*)d_in[2];
    const float* W1 = (const float*)d_in[3];
    const float* b1 = (const float*)d_in[4];
    const float* W2 = (const float*)d_in[5];
    const float* b2 = (const float*)d_in[6];
    float* out = (float*)d_out;

    repack_kv<<<(TT * CCH) / 256, 256>>>(Kp, Vp);
    precompute_U<<<TT / 128, 512>>>(y, W1, b1);
    rca_kernel<<<1, 512>>>(W1, W2, b2, out);
    scale_out<<<(CCH * TT) / 256, 256>>>(out);
}

// round 6
// speedup vs baseline: 1.6208x; 1.3671x over previous
#include <cuda_runtime.h>

#define CCH 512
#define TT  8192
#define MM  5
#define PLANE (TT * CCH)

// ---- static device scratch ----
__device__ float g_U[TT * 16];        // U[t,j] = b1[j] + W1^T y_t
__device__ float g_invd[TT];          // rsqrt(s_t)
__device__ float g_KVp[10 * PLANE];   // planar: plane m = K[:,:,m], plane 5+m = V[:,:,m]; [m][t][c]
__device__ float g_dotT[PLANE];       // raw dot, t-major [t][c]

// ---------------- repack K,V into planar layout ----------------
__global__ void repack_kv(const float* __restrict__ K, const float* __restrict__ V)
{
    const int idx = blockIdx.x * blockDim.x + threadIdx.x;   // t*512 + c
    const long b = (long)idx * 5;
#pragma unroll
    for (int m = 0; m < MM; m++) {
        g_KVp[m * PLANE + idx]       = K[b + m];
        g_KVp[(5 + m) * PLANE + idx] = V[b + m];
    }
}

// ---------------- precompute U (parallel) ----------------
__global__ void precompute_U(const float* __restrict__ y,
                             const float* __restrict__ W1,
                             const float* __restrict__ b1)
{
    const int j  = threadIdx.x & 15;
    const int t4 = blockIdx.x * 32 + (threadIdx.x >> 4);
    const int t0 = t4 * 4;
    const float bj = b1[j];
    float a0 = bj, a1 = bj, a2 = bj, a3 = bj;
#pragma unroll 8
    for (int c = 0; c < CCH; c++) {
        const float4 yv = *(const float4*)&y[c * TT + t0];
        const float w = W1[c * 16 + j];
        a0 = fmaf(yv.x, w, a0);
        a1 = fmaf(yv.y, w, a1);
        a2 = fmaf(yv.z, w, a2);
        a3 = fmaf(yv.w, w, a3);
    }
    g_U[(t0 + 0) * 16 + j] = a0;
    g_U[(t0 + 1) * 16 + j] = a1;
    g_U[(t0 + 2) * 16 + j] = a2;
    g_U[(t0 + 3) * 16 + j] = a3;
}

// ---------------- sequential recurrence, 1 CTA ----------------
__global__ __launch_bounds__(512, 1)
void rca_kernel(const float* __restrict__ W1,
                const float* __restrict__ W2,
                const float* __restrict__ b2)
{
    __shared__ float sdot[CCH];
    __shared__ float ss[16];
    __shared__ float sh[16];

    const int tid  = threadIdx.x;
    const int wid  = tid >> 5;
    const int lane = tid & 31;

    // B-phase channel mapping: lane handles c = 4*lane + 128*ii + k (conflict-free LDS.128)
    float w1r[16];
#pragma unroll
    for (int ii = 0; ii < 4; ii++)
#pragma unroll
        for (int k = 0; k < 4; k++)
            w1r[4 * ii + k] = W1[(4 * lane + 128 * ii + k) * 16 + wid];

    float w2r[16];
#pragma unroll
    for (int j = 0; j < 16; j++) w2r[j] = W2[j * CCH + tid];
    const float b2c = b2[tid];

    float e0 = 0.f, e1 = 0.f, e2 = 0.f, e3 = 0.f, e4 = 0.f;   // ema

    // depth-3 prefetch buffers (planar loads: 1 line per warp-LDG)
    float kb[3][MM], vb[3][MM], ub[3];
#pragma unroll
    for (int i = 0; i < 3; i++) {
        const int idx = i * CCH + tid;
#pragma unroll
        for (int m = 0; m < MM; m++) {
            kb[i][m] = g_KVp[m * PLANE + idx];
            vb[i][m] = g_KVp[(5 + m) * PLANE + idx];
        }
        ub[i] = g_U[i * 16 + wid];
    }

    sdot[tid] = 0.f;
    if (tid < 16) ss[tid] = 0.f;
    __syncthreads();

    const float4* sd4 = (const float4*)sdot;

    for (int t0 = 0; t0 < TT + 3; t0 += 3) {
#pragma unroll
        for (int i = 0; i < 3; i++) {
            const int t = t0 + i;

            // ---------- B: g[wid] = sum_c dot_prev[c]*W1[c,wid]; s = sum ema^2 ----------
            float g0 = 0.f, g1 = 0.f, g2 = 0.f, g3 = 0.f;
#pragma unroll
            for (int ii = 0; ii < 4; ii++) {
                const float4 d = sd4[lane + 32 * ii];
                g0 = fmaf(d.x, w1r[4 * ii + 0], g0);
                g1 = fmaf(d.y, w1r[4 * ii + 1], g1);
                g2 = fmaf(d.z, w1r[4 * ii + 2], g2);
                g3 = fmaf(d.w, w1r[4 * ii + 3], g3);
            }
            float g = (g0 + g1) + (g2 + g3);
            float s = ss[lane & 15];
            // interleaved butterflies: g (5 rounds), s (4 rounds)
            g += __shfl_xor_sync(0xffffffffu, g, 16);
            s += __shfl_xor_sync(0xffffffffu, s, 8);
            g += __shfl_xor_sync(0xffffffffu, g, 8);
            s += __shfl_xor_sync(0xffffffffu, s, 4);
            g += __shfl_xor_sync(0xffffffffu, g, 4);
            s += __shfl_xor_sync(0xffffffffu, s, 2);
            g += __shfl_xor_sync(0xffffffffu, g, 2);
            s += __shfl_xor_sync(0xffffffffu, s, 1);
            g += __shfl_xor_sync(0xffffffffu, g, 1);

            const float inv = rsqrtf(fmaxf(s, 1e-37f));
            if (lane == 0) {
                sh[wid] = fmaxf(fmaf(g, inv, ub[i]), 0.f);
                if (wid == 0 && t > 0) g_invd[t - 1] = inv;
            }
            if (t == TT) return;

            __syncthreads();   // sh visible; orders ss/sdot reads before A writes

            // ---------- C: q[c] = b2[c] + sum_j h[j]*W2[j,c] ----------
            const float4 h0 = *(const float4*)&sh[0];
            const float4 h1 = *(const float4*)&sh[4];
            const float4 h2 = *(const float4*)&sh[8];
            const float4 h3 = *(const float4*)&sh[12];
            float q0 = b2c, q1 = 0.f, q2 = 0.f, q3 = 0.f;
            q0 = fmaf(h0.x, w2r[0],  q0); q1 = fmaf(h0.y, w2r[1],  q1);
            q2 = fmaf(h0.z, w2r[2],  q2); q3 = fmaf(h0.w, w2r[3],  q3);
            q0 = fmaf(h1.x, w2r[4],  q0); q1 = fmaf(h1.y, w2r[5],  q1);
            q2 = fmaf(h1.z, w2r[6],  q2); q3 = fmaf(h1.w, w2r[7],  q3);
            q0 = fmaf(h2.x, w2r[8],  q0); q1 = fmaf(h2.y, w2r[9],  q1);
            q2 = fmaf(h2.z, w2r[10], q2); q3 = fmaf(h2.w, w2r[11], q3);
            q0 = fmaf(h3.x, w2r[12], q0); q1 = fmaf(h3.y, w2r[13], q1);
            q2 = fmaf(h3.z, w2r[14], q2); q3 = fmaf(h3.w, w2r[15], q3);
            const float qm = 0.05f * ((q0 + q1) + (q2 + q3));

            // ---------- A: ema update, dot, sp ----------
            e0 = fmaf(0.95f, e0, qm * kb[i][0]);
            e1 = fmaf(0.95f, e1, qm * kb[i][1]);
            e2 = fmaf(0.95f, e2, qm * kb[i][2]);
            e3 = fmaf(0.95f, e3, qm * kb[i][3]);
            e4 = fmaf(0.95f, e4, qm * kb[i][4]);
            float dot = e0 * vb[i][0];
            dot = fmaf(e1, vb[i][1], dot);
            dot = fmaf(e2, vb[i][2], dot);
            dot = fmaf(e3, vb[i][3], dot);
            dot = fmaf(e4, vb[i][4], dot);
            float sp = e0 * e0;
            sp = fmaf(e1, e1, sp);
            sp = fmaf(e2, e2, sp);
            sp = fmaf(e3, e3, sp);
            sp = fmaf(e4, e4, sp);

            sdot[tid] = dot;
            g_dotT[t * CCH + tid] = dot;   // coalesced raw store; scaled in post-pass

            // prefetch t+3 into this slot
            {
                const int tn  = (t + 3 < TT) ? (t + 3) : (TT - 1);
                const int idx = tn * CCH + tid;
#pragma unroll
                for (int m = 0; m < MM; m++) {
                    kb[i][m] = g_KVp[m * PLANE + idx];
                    vb[i][m] = g_KVp[(5 + m) * PLANE + idx];
                }
                ub[i] = g_U[tn * 16 + wid];
            }

            // warp-reduce sp -> ss[wid]
            sp += __shfl_xor_sync(0xffffffffu, sp, 16);
            sp += __shfl_xor_sync(0xffffffffu, sp, 8);
            sp += __shfl_xor_sync(0xffffffffu, sp, 4);
            sp += __shfl_xor_sync(0xffffffffu, sp, 2);
            sp += __shfl_xor_sync(0xffffffffu, sp, 1);
            if (lane == 0) ss[wid] = sp;

            __syncthreads();   // sdot/ss visible for next B
        }
    }
}

// ---------------- transpose + scale: out[c*TT+t] = dotT[t][c] * invd[t] ----------------
__global__ void transpose_scale(float* __restrict__ out)
{
    __shared__ float tile[32][33];
    const int t0 = blockIdx.x * 32;
    const int c0 = blockIdx.y * 32;
    const int tx = threadIdx.x;   // 0..31
    const int ty = threadIdx.y;   // 0..7

#pragma unroll
    for (int r = ty; r < 32; r += 8)   // r = local t
        tile[r][tx] = g_dotT[(t0 + r) * CCH + (c0 + tx)] * g_invd[t0 + r];
    __syncthreads();
#pragma unroll
    for (int r = ty; r < 32; r += 8)   // r = local c
        out[(long)(c0 + r) * TT + (t0 + tx)] = tile[tx][r];
}

extern "C" void kernel_launch(void* const* d_in, const int* in_sizes, int n_in,
                              void* d_out, int out_size) {
    const float* y  = (const float*)d_in[0];
    const float* Kp = (const float*)d_in[1];
    const float* Vp = (const float*)d_in[2];
    const float* W1 = (const float*)d_in[3];
    const float* b1 = (const float*)d_in[4];
    const float* W2 = (const float*)d_in[5];
    const float* b2 = (const float*)d_in[6];
    float* out = (float*)d_out;

    repack_kv<<<(TT * CCH) / 256, 256>>>(Kp, Vp);
    precompute_U<<<TT / 128, 512>>>(y, W1, b1);
    rca_kernel<<<1, 512>>>(W1, W2, b2);
    dim3 tb(32, 8);
    dim3 tg(TT / 32, CCH / 32);
    transpose_scale<<<tg, tb>>>(out);
}